// round 11
// baseline (speedup 1.0000x reference)
#include <cuda_runtime.h>
#include <cuda_bf16.h>
#include <cstdint>

#define BB 8
#define NN 50000
#define CC 8
#define CAP 2048
#define KP 1024
#define MAXD 100
#define SCORE_THR 0.99f

typedef unsigned long long u64;
typedef unsigned int u32;

// ---------------- device scratch (no allocations allowed) -------------------
__device__ int   g_cnt[BB * CC];          // zero at load; re-zeroed by k3_rank
__device__ float g_cscore[BB * CC * CAP];
__device__ int   g_cidx[BB * CC * CAP];

__device__ int   g_M[BB * CC];
__device__ float g_sx1[BB * CC * KP];     // .bss zero: rows >= M stay 0 forever
__device__ float g_sy1[BB * CC * KP];
__device__ float g_sx2[BB * CC * KP];
__device__ float g_sy2[BB * CC * KP];
__device__ float g_sar[BB * CC * KP];
__device__ u64   g_skey[BB * CC * KP];
__device__ int   g_sidx[BB * CC * KP];

__device__ u32   g_mask[BB * CC * KP * 32];  // 8 MB; unwritten words stay 0
__device__ u32   g_diag[BB * CC * KP];       // diag word of each row (256 KB)

__device__ int   g_kcnt[BB * CC];
__device__ u64   g_ckey[BB * CC * 128];
__device__ int   g_cidxsel[BB * CC * 128];

// ---------------------------------------------------------------------------
// Candidate compaction: 2 points/thread, one batched atomic warp-instr.
__global__ void __launch_bounds__(256) k1_cand(const float* __restrict__ cls) {
    int b  = blockIdx.y;
    int t  = threadIdx.x;
    int n0 = blockIdx.x * 512 + t;       // always < NN for grid.x = 98
    int n1 = n0 + 256;
    bool ok1 = n1 < NN;

    float a[8], dd[8];
    {
        const float4* p = reinterpret_cast<const float4*>(cls + ((size_t)b * NN + n0) * CC);
        float4 x = p[0], y = p[1];
        a[0]=x.x; a[1]=x.y; a[2]=x.z; a[3]=x.w;
        a[4]=y.x; a[5]=y.y; a[6]=y.z; a[7]=y.w;
    }
    if (ok1) {
        const float4* p = reinterpret_cast<const float4*>(cls + ((size_t)b * NN + n1) * CC);
        float4 x = p[0], y = p[1];
        dd[0]=x.x; dd[1]=x.y; dd[2]=x.z; dd[3]=x.w;
        dd[4]=y.x; dd[5]=y.y; dd[6]=y.z; dd[7]=y.w;
    } else {
#pragma unroll
        for (int c = 0; c < 8; c++) dd[c] = 0.0f;
    }

    int lane = t & 31;
    u32 m0[8], m1[8];
    u32 myc0 = 0, myc1 = 0;
#pragma unroll
    for (int c = 0; c < 8; c++) {
        m0[c] = __ballot_sync(0xffffffffu, a[c]  > SCORE_THR);
        m1[c] = __ballot_sync(0xffffffffu, dd[c] > SCORE_THR);
        if (lane == c) { myc0 = m0[c]; myc1 = m1[c]; }
    }
    int tot = __popc(myc0) + __popc(myc1);
    int base = 0;
    if (lane < 8 && tot > 0) base = atomicAdd(&g_cnt[b * 8 + lane], tot);
    u32 lt = (1u << lane) - 1u;
#pragma unroll
    for (int c = 0; c < 8; c++) {
        int basec = __shfl_sync(0xffffffffu, base, c);
        int bcC = (b * 8 + c) * CAP;
        if (a[c] > SCORE_THR) {
            int off = basec + __popc(m0[c] & lt);
            if (off < CAP) { g_cscore[bcC + off] = a[c]; g_cidx[bcC + off] = n0; }
        }
        if (dd[c] > SCORE_THR) {
            int off = basec + __popc(m0[c]) + __popc(m1[c] & lt);
            if (off < CAP) { g_cscore[bcC + off] = dd[c]; g_cidx[bcC + off] = n1; }
        }
    }
}

// ---------------------------------------------------------------------------
__device__ __forceinline__ void bitonic_desc(u64* s, int n, int tid, int nthreads) {
    for (int k = 2; k <= n; k <<= 1) {
        for (int j = k >> 1; j > 0; j >>= 1) {
            for (int i = tid; i < n; i += nthreads) {
                int ixj = i ^ j;
                if (ixj > i) {
                    u64 a = s[i], c = s[ixj];
                    bool up = ((i & k) == 0);
                    if (up ? (a < c) : (a > c)) { s[i] = c; s[ixj] = a; }
                }
            }
            __syncthreads();
        }
    }
}

// ---------------------------------------------------------------------------
// Sort candidates (size = next pow2 of cnt) + write sorted box data.
__global__ void __launch_bounds__(512) k2a_sort(const float* __restrict__ boxes) {
    __shared__ u64 keys[CAP];
    int bc = blockIdx.x;
    int b  = bc >> 3;
    int tid = threadIdx.x;

    int cnt = g_cnt[bc];
    if (cnt > CAP) cnt = CAP;
    int P = 64;
    while (P < cnt) P <<= 1;

    for (int t = tid; t < P; t += 512) {
        u64 k = 0ull;
        if (t < cnt) {
            u32 sb = __float_as_uint(g_cscore[bc * CAP + t]);
            u32 iv = ~(u32)g_cidx[bc * CAP + t];
            k = ((u64)sb << 32) | (u64)iv;
        }
        keys[t] = k;
    }
    __syncthreads();
    bitonic_desc(keys, P, tid, 512);

    int M = cnt < KP ? cnt : KP;
    if (tid == 0) g_M[bc] = M;

    for (int t = tid; t < M; t += 512) {
        u64 kk = keys[t];
        int idx = (int)(~(u32)kk);
        float4 bp = reinterpret_cast<const float4*>(boxes)[(size_t)(b * NN + idx)];
        int o = bc * KP + t;
        g_sx1[o] = bp.x; g_sy1[o] = bp.y; g_sx2[o] = bp.z; g_sy2[o] = bp.w;
        g_sar[o] = __fmul_rn(__fsub_rn(bp.z, bp.x), __fsub_rn(bp.w, bp.y));
        g_skey[o] = kk;
        g_sidx[o] = idx;
    }
}

// ---------------------------------------------------------------------------
// Triangular IoU mask build, item = (iw, jw) 32x32 tile, 128 slots per bc.
// Division-free exact test: rn(inter/den) > 0.5  <=>  inter - 0.5*den > (0.5*den)*2^-24
#define NSPLIT 16

__global__ void __launch_bounds__(256) k2b_mask() {
    __shared__ float sx1[KP], sy1[KP], sx2[KP], sy2[KP], sar[KP];
    int bc = blockIdx.x >> 4;
    int s  = blockIdx.x & 15;
    int M  = g_M[bc];
    int nW = (M + 31) >> 5;

    for (int t = threadIdx.x; t < KP; t += 256) {
        int o = bc * KP + t;        // rows >= M are zero in global (.bss, never written)
        sx1[t] = g_sx1[o]; sy1[t] = g_sy1[o];
        sx2[t] = g_sx2[o]; sy2[t] = g_sy2[o];
        sar[t] = g_sar[o];
    }
    __syncthreads();

    int w = threadIdx.x >> 5, lane = threadIdx.x & 31;
    int slot = s * 8 + w;            // 0..127
    int e = 0;
    for (int iw = 0; iw < nW; iw++) {
        for (int jw = iw; jw < nW; jw++, e++) {
            if ((e & 127) != slot) continue;
            int j = (jw << 5) + lane;
            float jx1 = sx1[j], jy1 = sy1[j], jx2 = sx2[j], jy2 = sy2[j], ja = sar[j];
            int i0 = iw << 5;
            int dmax = M - i0; if (dmax > 32) dmax = 32;
            bool isdiag = (jw == iw);
            for (int d = 0; d < dmax; d++) {
                int i = i0 + d;
                float ix1 = sx1[i], iy1 = sy1[i], ix2 = sx2[i], iy2 = sy2[i], ia = sar[i];
                float ww = fmaxf(__fsub_rn(fminf(ix2, jx2), fmaxf(ix1, jx1)), 0.0f);
                float hh = fmaxf(__fsub_rn(fminf(iy2, jy2), fmaxf(iy1, jy1)), 0.0f);
                float inter = __fmul_rn(ww, hh);
                float den   = __fsub_rn(__fadd_rn(ia, ja), inter);
                float th    = __fmul_rn(0.5f, den);          // exact
                float diff  = __fsub_rn(inter, th);          // exact (Sterbenz)
                float eps   = __fmul_rn(th, 5.9604645e-8f);  // t * 2^-24, exact
                bool p = (j > i) && (j < M) && (diff > eps);
                u32 mm = __ballot_sync(0xffffffffu, p);
                if (lane == 0) {
                    g_mask[((size_t)bc << 15) + (i << 5) + jw] = mm;
                    if (isdiag) g_diag[(bc << 10) + i] = mm;
                }
            }
        }
    }
}

// ---------------------------------------------------------------------------
// Serial greedy scan: one warp per (b,c).
// Phase A: dg-only chain from compact g_diag (double-buffered, 32 regs).
// Phase B: deferred remv |= row for kept elements (independent loads, MLP).
__global__ void __launch_bounds__(32) k2c_scan() {
    int bc   = blockIdx.x;
    int lane = threadIdx.x;
    int c    = bc & 7;
    int M    = g_M[bc];
    if (M == 0) { if (lane == 0) g_kcnt[bc] = 0; return; }
    int nW = (M + 31) >> 5;
    int lastg = (M - 1) >> 5;
    u32 tailm = (M & 31) ? ((1u << (M & 31)) - 1u) : 0xffffffffu;

    const u32* mrow = g_mask + ((size_t)bc << 15);
    const u32* diag = g_diag + (bc << 10);

    u32 DGA[32], DGB[32];
#pragma unroll
    for (int d = 0; d < 32; d++) DGA[d] = diag[d];   // group 0 (rows >= M are 0)

    u32 remv = 0u, keepreg = 0u;
    for (int g1 = 0; g1 < nW; g1++) {
        // prefetch next group's diagonal words (hidden under phase A/B)
        int nb = (g1 + 1 < nW) ? ((g1 + 1) << 5) : 0;
#pragma unroll
        for (int d = 0; d < 32; d++) DGB[d] = diag[nb + d];

        u32 cur = __shfl_sync(0xffffffffu, remv, g1);
        u32 kw = 0u;
#pragma unroll
        for (int d = 0; d < 32; d++) {
            u32 smask = (u32)((int)(cur << (31 - d)) >> 31);  // all-ones if suppressed
            kw  |= ~smask & (1u << d);
            cur |= DGA[d] & ~smask;
        }
        if (lane == g1) keepreg = kw;

        // phase B: OR kept rows into remv (independent broadcast loads)
        u32 wb = kw;
        if (g1 == lastg) wb &= tailm;
        int rbase = (g1 << 10) + lane;
        while (wb) {
            int d = __ffs(wb) - 1;
            wb &= wb - 1;
            remv |= mrow[rbase + (d << 5)];
        }
#pragma unroll
        for (int d = 0; d < 32; d++) DGA[d] = DGB[d];
    }
    // mask tail bits beyond M
    if (lane == lastg) keepreg &= tailm;
    if (lane > lastg)  keepreg = 0u;

    // compact kept entries (order preserved -> score-sorted), cap 128
    int cntl = __popc(keepreg);
    int pre = cntl;
#pragma unroll
    for (int o = 1; o < 32; o <<= 1) {
        int vv = __shfl_up_sync(0xffffffffu, pre, o);
        if (lane >= o) pre += vv;
    }
    int off = pre - cntl;
    int total = __shfl_sync(0xffffffffu, pre, 31);
    if (lane == 0) g_kcnt[bc] = total < 128 ? total : 128;
    u32 wb = keepreg;
    while (wb && off < 128) {
        int b2 = __ffs(wb) - 1;
        wb &= wb - 1;
        int i = (lane << 5) + b2;
        u64 sk = g_skey[bc * KP + i];
        g_ckey[bc * 128 + off]    = (sk & 0xffffffff00000000ull) | (u64)(~(u32)(c * KP + i));
        g_cidxsel[bc * 128 + off] = g_sidx[bc * KP + i];
        off++;
    }
}

// ---------------------------------------------------------------------------
// Final top-100 by parallel rank-selection over 8 sorted lists of <=128.
__global__ void __launch_bounds__(1024) k3_rank(const float* __restrict__ boxes,
                                                const float* __restrict__ rot,
                                                const float* __restrict__ trans,
                                                float* __restrict__ out) {
    __shared__ u64 lists[8][128];
    __shared__ int written[MAXD];
    int b = blockIdx.x, tid = threadIdx.x;
    int c = tid >> 7, k = tid & 127;
    int bc = b * 8 + c;

    if (tid < 8)    g_cnt[b * 8 + tid] = 0;   // reset for next graph replay
    if (tid < MAXD) written[tid] = 0;

    u64 key = 0ull;
    if (k < g_kcnt[bc]) key = g_ckey[bc * 128 + k];
    lists[c][k] = key;
    __syncthreads();

    float* ob   = out;
    float* os   = out + 3200;
    float* ol   = out + 4000;
    float* orot = out + 4800;
    float* otr  = out + 7200;

    if (key != 0ull) {
        int rank = 0;
#pragma unroll
        for (int c2 = 0; c2 < 8; c2++) {
            const u64* L = lists[c2];
            int lo = 0, hi = 128;
#pragma unroll
            for (int s = 0; s < 8; s++) {
                if (lo < hi) {
                    int mid = (lo + hi) >> 1;
                    if (L[mid] > key) lo = mid + 1; else hi = mid;
                }
            }
            rank += lo;   // count of entries strictly greater than key
        }
        if (rank < MAXD) {
            written[rank] = 1;
            int base = b * MAXD + rank;
            int idx  = g_cidxsel[bc * 128 + k];
            float s  = __uint_as_float((u32)(key >> 32));
            size_t g = (size_t)(b * NN + idx);
            float4 bp = reinterpret_cast<const float4*>(boxes)[g];
            ob[base * 4 + 0] = bp.x;
            ob[base * 4 + 1] = bp.y;
            ob[base * 4 + 2] = bp.z;
            ob[base * 4 + 3] = bp.w;
            os[base] = s;
            ol[base] = (float)c;
            const float* rp = rot + g * 3;
            orot[base * 3 + 0] = rp[0];
            orot[base * 3 + 1] = rp[1];
            orot[base * 3 + 2] = rp[2];
            const float* tp = trans + g * 3;
            otr[base * 3 + 0] = tp[0];
            otr[base * 3 + 1] = tp[1];
            otr[base * 3 + 2] = tp[2];
        }
    }
    __syncthreads();
    if (tid < MAXD && !written[tid]) {
        int base = b * MAXD + tid;
        ob[base * 4 + 0] = -1.0f;
        ob[base * 4 + 1] = -1.0f;
        ob[base * 4 + 2] = -1.0f;
        ob[base * 4 + 3] = -1.0f;
        os[base] = -1.0f;
        ol[base] = -1.0f;
        orot[base * 3 + 0] = -1.0f;
        orot[base * 3 + 1] = -1.0f;
        orot[base * 3 + 2] = -1.0f;
        otr[base * 3 + 0] = -1.0f;
        otr[base * 3 + 1] = -1.0f;
        otr[base * 3 + 2] = -1.0f;
    }
}

// ---------------------------------------------------------------------------
extern "C" void kernel_launch(void* const* d_in, const int* in_sizes, int n_in,
                              void* d_out, int out_size) {
    const float* boxes = (const float*)d_in[0];
    const float* cls   = (const float*)d_in[1];
    const float* rot   = (const float*)d_in[2];
    const float* trans = (const float*)d_in[3];
    float* out = (float*)d_out;

    k1_cand<<<dim3((NN + 511) / 512, BB), 256>>>(cls);
    k2a_sort<<<BB * CC, 512>>>(boxes);
    k2b_mask<<<BB * CC * NSPLIT, 256>>>();
    k2c_scan<<<BB * CC, 32>>>();
    k3_rank<<<BB, 1024>>>(boxes, rot, trans, out);
}

// round 12
// speedup vs baseline: 3.4904x; 3.4904x over previous
#include <cuda_runtime.h>
#include <cuda_bf16.h>
#include <cstdint>

#define BB 8
#define NN 50000
#define CC 8
#define CAP 2048
#define KP 1024
#define KPAD 1056            // KP + 32 pad rows (always zero) -> clamp-free ring
#define MAXD 100
#define SCORE_THR 0.99f

typedef unsigned long long u64;
typedef unsigned int u32;

// ---------------- device scratch (no allocations allowed) -------------------
__device__ int   g_cnt[BB * CC];          // zero at load; re-zeroed by k3_rank
__device__ float g_cscore[BB * CC * CAP];
__device__ int   g_cidx[BB * CC * CAP];

__device__ int   g_M[BB * CC];
__device__ float g_sx1[BB * CC * KP];     // .bss zero: rows >= M stay 0 forever
__device__ float g_sy1[BB * CC * KP];
__device__ float g_sx2[BB * CC * KP];
__device__ float g_sy2[BB * CC * KP];
__device__ float g_sar[BB * CC * KP];
__device__ u64   g_skey[BB * CC * KP];
__device__ int   g_sidx[BB * CC * KP];

__device__ u32   g_mask[BB * CC * KPAD * 32];  // ~8.6 MB; unwritten words stay 0
__device__ u32   g_diag[BB * CC * KPAD];       // diag word of each row

__device__ int   g_kcnt[BB * CC];
__device__ u64   g_ckey[BB * CC * 128];
__device__ int   g_cidxsel[BB * CC * 128];

// ---------------------------------------------------------------------------
// Candidate compaction: 2 points/thread, one batched atomic warp-instr.
__global__ void __launch_bounds__(256) k1_cand(const float* __restrict__ cls) {
    int b  = blockIdx.y;
    int t  = threadIdx.x;
    int n0 = blockIdx.x * 512 + t;       // always < NN for grid.x = 98
    int n1 = n0 + 256;
    bool ok1 = n1 < NN;

    float a[8], dd[8];
    {
        const float4* p = reinterpret_cast<const float4*>(cls + ((size_t)b * NN + n0) * CC);
        float4 x = p[0], y = p[1];
        a[0]=x.x; a[1]=x.y; a[2]=x.z; a[3]=x.w;
        a[4]=y.x; a[5]=y.y; a[6]=y.z; a[7]=y.w;
    }
    if (ok1) {
        const float4* p = reinterpret_cast<const float4*>(cls + ((size_t)b * NN + n1) * CC);
        float4 x = p[0], y = p[1];
        dd[0]=x.x; dd[1]=x.y; dd[2]=x.z; dd[3]=x.w;
        dd[4]=y.x; dd[5]=y.y; dd[6]=y.z; dd[7]=y.w;
    } else {
#pragma unroll
        for (int c = 0; c < 8; c++) dd[c] = 0.0f;
    }

    int lane = t & 31;
    u32 m0[8], m1[8];
    u32 myc0 = 0, myc1 = 0;
#pragma unroll
    for (int c = 0; c < 8; c++) {
        m0[c] = __ballot_sync(0xffffffffu, a[c]  > SCORE_THR);
        m1[c] = __ballot_sync(0xffffffffu, dd[c] > SCORE_THR);
        if (lane == c) { myc0 = m0[c]; myc1 = m1[c]; }
    }
    int tot = __popc(myc0) + __popc(myc1);
    int base = 0;
    if (lane < 8 && tot > 0) base = atomicAdd(&g_cnt[b * 8 + lane], tot);
    u32 lt = (1u << lane) - 1u;
#pragma unroll
    for (int c = 0; c < 8; c++) {
        int basec = __shfl_sync(0xffffffffu, base, c);
        int bcC = (b * 8 + c) * CAP;
        if (a[c] > SCORE_THR) {
            int off = basec + __popc(m0[c] & lt);
            if (off < CAP) { g_cscore[bcC + off] = a[c]; g_cidx[bcC + off] = n0; }
        }
        if (dd[c] > SCORE_THR) {
            int off = basec + __popc(m0[c]) + __popc(m1[c] & lt);
            if (off < CAP) { g_cscore[bcC + off] = dd[c]; g_cidx[bcC + off] = n1; }
        }
    }
}

// ---------------------------------------------------------------------------
__device__ __forceinline__ void bitonic_desc(u64* s, int n, int tid, int nthreads) {
    for (int k = 2; k <= n; k <<= 1) {
        for (int j = k >> 1; j > 0; j >>= 1) {
            for (int i = tid; i < n; i += nthreads) {
                int ixj = i ^ j;
                if (ixj > i) {
                    u64 a = s[i], c = s[ixj];
                    bool up = ((i & k) == 0);
                    if (up ? (a < c) : (a > c)) { s[i] = c; s[ixj] = a; }
                }
            }
            __syncthreads();
        }
    }
}

// ---------------------------------------------------------------------------
// Sort candidates (size = next pow2 of cnt) + write sorted box data.
__global__ void __launch_bounds__(512) k2a_sort(const float* __restrict__ boxes) {
    __shared__ u64 keys[CAP];
    int bc = blockIdx.x;
    int b  = bc >> 3;
    int tid = threadIdx.x;

    int cnt = g_cnt[bc];
    if (cnt > CAP) cnt = CAP;
    int P = 64;
    while (P < cnt) P <<= 1;

    for (int t = tid; t < P; t += 512) {
        u64 k = 0ull;
        if (t < cnt) {
            u32 sb = __float_as_uint(g_cscore[bc * CAP + t]);
            u32 iv = ~(u32)g_cidx[bc * CAP + t];
            k = ((u64)sb << 32) | (u64)iv;
        }
        keys[t] = k;
    }
    __syncthreads();
    bitonic_desc(keys, P, tid, 512);

    int M = cnt < KP ? cnt : KP;
    if (tid == 0) g_M[bc] = M;

    for (int t = tid; t < M; t += 512) {
        u64 kk = keys[t];
        int idx = (int)(~(u32)kk);
        float4 bp = reinterpret_cast<const float4*>(boxes)[(size_t)(b * NN + idx)];
        int o = bc * KP + t;
        g_sx1[o] = bp.x; g_sy1[o] = bp.y; g_sx2[o] = bp.z; g_sy2[o] = bp.w;
        g_sar[o] = __fmul_rn(__fsub_rn(bp.z, bp.x), __fsub_rn(bp.w, bp.y));
        g_skey[o] = kk;
        g_sidx[o] = idx;
    }
}

// ---------------------------------------------------------------------------
// Triangular IoU mask build, item = (iw, jw) 32x32 tile, 128 slots per bc.
// Division-free exact test: rn(inter/den) > 0.5  <=>  inter - 0.5*den > (0.5*den)*2^-24
#define NSPLIT 16

__global__ void __launch_bounds__(256) k2b_mask() {
    __shared__ float sx1[KP], sy1[KP], sx2[KP], sy2[KP], sar[KP];
    int bc = blockIdx.x >> 4;
    int s  = blockIdx.x & 15;
    int M  = g_M[bc];
    int nW = (M + 31) >> 5;

    for (int t = threadIdx.x; t < KP; t += 256) {
        int o = bc * KP + t;        // rows >= M are zero in global (.bss, never written)
        sx1[t] = g_sx1[o]; sy1[t] = g_sy1[o];
        sx2[t] = g_sx2[o]; sy2[t] = g_sy2[o];
        sar[t] = g_sar[o];
    }
    __syncthreads();

    int w = threadIdx.x >> 5, lane = threadIdx.x & 31;
    int slot = s * 8 + w;            // 0..127
    int e = 0;
    for (int iw = 0; iw < nW; iw++) {
        for (int jw = iw; jw < nW; jw++, e++) {
            if ((e & 127) != slot) continue;
            int j = (jw << 5) + lane;
            float jx1 = sx1[j], jy1 = sy1[j], jx2 = sx2[j], jy2 = sy2[j], ja = sar[j];
            int i0 = iw << 5;
            int dmax = M - i0; if (dmax > 32) dmax = 32;
            bool isdiag = (jw == iw);
            for (int d = 0; d < dmax; d++) {
                int i = i0 + d;
                float ix1 = sx1[i], iy1 = sy1[i], ix2 = sx2[i], iy2 = sy2[i], ia = sar[i];
                float ww = fmaxf(__fsub_rn(fminf(ix2, jx2), fmaxf(ix1, jx1)), 0.0f);
                float hh = fmaxf(__fsub_rn(fminf(iy2, jy2), fmaxf(iy1, jy1)), 0.0f);
                float inter = __fmul_rn(ww, hh);
                float den   = __fsub_rn(__fadd_rn(ia, ja), inter);
                float th    = __fmul_rn(0.5f, den);          // exact
                float diff  = __fsub_rn(inter, th);          // exact (Sterbenz)
                float eps   = __fmul_rn(th, 5.9604645e-8f);  // t * 2^-24, exact
                bool p = (j > i) && (j < M) && (diff > eps);
                u32 mm = __ballot_sync(0xffffffffu, p);
                if (lane == 0) {
                    g_mask[((size_t)bc * KPAD + i) * 32 + jw] = mm;
                    if (isdiag) g_diag[bc * KPAD + i] = mm;
                }
            }
        }
    }
}

// ---------------------------------------------------------------------------
// Serial greedy scan: one warp per (b,c), 32-deep RW prefetch ring (MLP=32),
// DG from compact g_diag, clamp-free thanks to 32 zero pad rows.
__global__ void __launch_bounds__(32) k2c_scan() {
    int bc   = blockIdx.x;
    int lane = threadIdx.x;
    int c    = bc & 7;
    int M    = g_M[bc];
    if (M == 0) { if (lane == 0) g_kcnt[bc] = 0; return; }
    int nW = (M + 31) >> 5;

    const u32* mrow = g_mask + (size_t)bc * KPAD * 32;
    const u32* diag = g_diag + bc * KPAD;

    u32 RW[32], DG[32];
#pragma unroll
    for (int d = 0; d < 32; d++) {
        RW[d] = mrow[(d << 5) + lane];
        DG[d] = diag[d];
    }
    u32 remv = 0u, keepreg = 0u;
    for (int g1 = 0; g1 < nW; g1++) {
        u32 cur = __shfl_sync(0xffffffffu, remv, g1);
        u32 kw = 0u;
#pragma unroll
        for (int d = 0; d < 32; d++) {
            int i = (g1 << 5) + d;
            u32 rw = RW[d], dg = DG[d];
            int ip = i + 32;                       // <= 1055 < KPAD, pad rows are 0
            RW[d] = mrow[(ip << 5) + lane];
            DG[d] = diag[ip];
            u32 smask = (u32)((int)(cur << (31 - d)) >> 31);  // all-ones if suppressed
            kw   |= ~smask & (1u << d);
            cur  |= dg & ~smask;
            remv |= rw & ~smask;
        }
        if (lane == g1) keepreg = kw;
    }
    // mask tail bits beyond M
    {
        int lastg = (M - 1) >> 5;
        u32 tail = (M & 31) ? ((1u << (M & 31)) - 1u) : 0xffffffffu;
        if (lane == lastg) keepreg &= tail;
        if (lane > lastg)  keepreg = 0u;
    }

    // compact kept entries (order preserved -> score-sorted), cap 128
    int cntl = __popc(keepreg);
    int pre = cntl;
#pragma unroll
    for (int o = 1; o < 32; o <<= 1) {
        int vv = __shfl_up_sync(0xffffffffu, pre, o);
        if (lane >= o) pre += vv;
    }
    int off = pre - cntl;
    int total = __shfl_sync(0xffffffffu, pre, 31);
    if (lane == 0) g_kcnt[bc] = total < 128 ? total : 128;
    u32 wb = keepreg;
    while (wb && off < 128) {
        int b2 = __ffs(wb) - 1;
        wb &= wb - 1;
        int i = (lane << 5) + b2;
        u64 sk = g_skey[bc * KP + i];
        g_ckey[bc * 128 + off]    = (sk & 0xffffffff00000000ull) | (u64)(~(u32)(c * KP + i));
        g_cidxsel[bc * 128 + off] = g_sidx[bc * KP + i];
        off++;
    }
}

// ---------------------------------------------------------------------------
// Final top-100 by parallel rank-selection over 8 sorted lists of <=128.
__global__ void __launch_bounds__(1024) k3_rank(const float* __restrict__ boxes,
                                                const float* __restrict__ rot,
                                                const float* __restrict__ trans,
                                                float* __restrict__ out) {
    __shared__ u64 lists[8][128];
    __shared__ int written[MAXD];
    int b = blockIdx.x, tid = threadIdx.x;
    int c = tid >> 7, k = tid & 127;
    int bc = b * 8 + c;

    if (tid < 8)    g_cnt[b * 8 + tid] = 0;   // reset for next graph replay
    if (tid < MAXD) written[tid] = 0;

    u64 key = 0ull;
    if (k < g_kcnt[bc]) key = g_ckey[bc * 128 + k];
    lists[c][k] = key;
    __syncthreads();

    float* ob   = out;
    float* os   = out + 3200;
    float* ol   = out + 4000;
    float* orot = out + 4800;
    float* otr  = out + 7200;

    if (key != 0ull) {
        int rank = 0;
#pragma unroll
        for (int c2 = 0; c2 < 8; c2++) {
            const u64* L = lists[c2];
            int lo = 0, hi = 128;
#pragma unroll
            for (int s = 0; s < 8; s++) {
                if (lo < hi) {
                    int mid = (lo + hi) >> 1;
                    if (L[mid] > key) lo = mid + 1; else hi = mid;
                }
            }
            rank += lo;   // count of entries strictly greater than key
        }
        if (rank < MAXD) {
            written[rank] = 1;
            int base = b * MAXD + rank;
            int idx  = g_cidxsel[bc * 128 + k];
            float s  = __uint_as_float((u32)(key >> 32));
            size_t g = (size_t)(b * NN + idx);
            float4 bp = reinterpret_cast<const float4*>(boxes)[g];
            ob[base * 4 + 0] = bp.x;
            ob[base * 4 + 1] = bp.y;
            ob[base * 4 + 2] = bp.z;
            ob[base * 4 + 3] = bp.w;
            os[base] = s;
            ol[base] = (float)c;
            const float* rp = rot + g * 3;
            orot[base * 3 + 0] = rp[0];
            orot[base * 3 + 1] = rp[1];
            orot[base * 3 + 2] = rp[2];
            const float* tp = trans + g * 3;
            otr[base * 3 + 0] = tp[0];
            otr[base * 3 + 1] = tp[1];
            otr[base * 3 + 2] = tp[2];
        }
    }
    __syncthreads();
    if (tid < MAXD && !written[tid]) {
        int base = b * MAXD + tid;
        ob[base * 4 + 0] = -1.0f;
        ob[base * 4 + 1] = -1.0f;
        ob[base * 4 + 2] = -1.0f;
        ob[base * 4 + 3] = -1.0f;
        os[base] = -1.0f;
        ol[base] = -1.0f;
        orot[base * 3 + 0] = -1.0f;
        orot[base * 3 + 1] = -1.0f;
        orot[base * 3 + 2] = -1.0f;
        otr[base * 3 + 0] = -1.0f;
        otr[base * 3 + 1] = -1.0f;
        otr[base * 3 + 2] = -1.0f;
    }
}

// ---------------------------------------------------------------------------
extern "C" void kernel_launch(void* const* d_in, const int* in_sizes, int n_in,
                              void* d_out, int out_size) {
    const float* boxes = (const float*)d_in[0];
    const float* cls   = (const float*)d_in[1];
    const float* rot   = (const float*)d_in[2];
    const float* trans = (const float*)d_in[3];
    float* out = (float*)d_out;

    k1_cand<<<dim3((NN + 511) / 512, BB), 256>>>(cls);
    k2a_sort<<<BB * CC, 512>>>(boxes);
    k2b_mask<<<BB * CC * NSPLIT, 256>>>();
    k2c_scan<<<BB * CC, 32>>>();
    k3_rank<<<BB, 1024>>>(boxes, rot, trans, out);
}

// round 13
// speedup vs baseline: 3.7649x; 1.0786x over previous
#include <cuda_runtime.h>
#include <cuda_bf16.h>
#include <cstdint>

#define BB 8
#define NN 50000
#define CC 8
#define CAP 2048
#define KP 1024
#define KPAD 1056            // KP + 32 pad rows (always zero) -> clamp-free ring
#define MAXD 100
#define SCORE_THR 0.99f

typedef unsigned long long u64;
typedef unsigned int u32;

// ---------------- device scratch (no allocations allowed) -------------------
__device__ int   g_cnt[BB * CC];          // zero at load; re-zeroed by k3_rank
__device__ float g_cscore[BB * CC * CAP];
__device__ int   g_cidx[BB * CC * CAP];

__device__ int   g_M[BB * CC];
__device__ float g_sx1[BB * CC * KP];     // .bss zero: rows >= M stay 0 forever
__device__ float g_sy1[BB * CC * KP];
__device__ float g_sx2[BB * CC * KP];
__device__ float g_sy2[BB * CC * KP];
__device__ float g_sar[BB * CC * KP];
__device__ u64   g_skey[BB * CC * KP];
__device__ int   g_sidx[BB * CC * KP];

__device__ u32   g_mask[BB * CC * KPAD * 32];  // ~8.6 MB; unwritten words stay 0
__device__ u32   g_diag[BB * CC * KPAD];       // diag word of each row

__device__ int   g_kcnt[BB * CC];
__device__ u64   g_ckey[BB * CC * 128];
__device__ int   g_cidxsel[BB * CC * 128];

// ---------------------------------------------------------------------------
// Candidate compaction: 2 points/thread, one batched atomic warp-instr.
__global__ void __launch_bounds__(256) k1_cand(const float* __restrict__ cls) {
    int b  = blockIdx.y;
    int t  = threadIdx.x;
    int n0 = blockIdx.x * 512 + t;       // always < NN for grid.x = 98
    int n1 = n0 + 256;
    bool ok1 = n1 < NN;

    float a[8], dd[8];
    {
        const float4* p = reinterpret_cast<const float4*>(cls + ((size_t)b * NN + n0) * CC);
        float4 x = p[0], y = p[1];
        a[0]=x.x; a[1]=x.y; a[2]=x.z; a[3]=x.w;
        a[4]=y.x; a[5]=y.y; a[6]=y.z; a[7]=y.w;
    }
    if (ok1) {
        const float4* p = reinterpret_cast<const float4*>(cls + ((size_t)b * NN + n1) * CC);
        float4 x = p[0], y = p[1];
        dd[0]=x.x; dd[1]=x.y; dd[2]=x.z; dd[3]=x.w;
        dd[4]=y.x; dd[5]=y.y; dd[6]=y.z; dd[7]=y.w;
    } else {
#pragma unroll
        for (int c = 0; c < 8; c++) dd[c] = 0.0f;
    }

    int lane = t & 31;
    u32 m0[8], m1[8];
    u32 myc0 = 0, myc1 = 0;
#pragma unroll
    for (int c = 0; c < 8; c++) {
        m0[c] = __ballot_sync(0xffffffffu, a[c]  > SCORE_THR);
        m1[c] = __ballot_sync(0xffffffffu, dd[c] > SCORE_THR);
        if (lane == c) { myc0 = m0[c]; myc1 = m1[c]; }
    }
    int tot = __popc(myc0) + __popc(myc1);
    int base = 0;
    if (lane < 8 && tot > 0) base = atomicAdd(&g_cnt[b * 8 + lane], tot);
    u32 lt = (1u << lane) - 1u;
#pragma unroll
    for (int c = 0; c < 8; c++) {
        int basec = __shfl_sync(0xffffffffu, base, c);
        int bcC = (b * 8 + c) * CAP;
        if (a[c] > SCORE_THR) {
            int off = basec + __popc(m0[c] & lt);
            if (off < CAP) { g_cscore[bcC + off] = a[c]; g_cidx[bcC + off] = n0; }
        }
        if (dd[c] > SCORE_THR) {
            int off = basec + __popc(m0[c]) + __popc(m1[c] & lt);
            if (off < CAP) { g_cscore[bcC + off] = dd[c]; g_cidx[bcC + off] = n1; }
        }
    }
}

// ---------------------------------------------------------------------------
__device__ __forceinline__ void bitonic_desc(u64* s, int n, int tid, int nthreads) {
    for (int k = 2; k <= n; k <<= 1) {
        for (int j = k >> 1; j > 0; j >>= 1) {
            for (int i = tid; i < n; i += nthreads) {
                int ixj = i ^ j;
                if (ixj > i) {
                    u64 a = s[i], c = s[ixj];
                    bool up = ((i & k) == 0);
                    if (up ? (a < c) : (a > c)) { s[i] = c; s[ixj] = a; }
                }
            }
            __syncthreads();
        }
    }
}

// ---------------------------------------------------------------------------
// Sort candidates (size = next pow2 of cnt) + write sorted box data.
__global__ void __launch_bounds__(512) k2a_sort(const float* __restrict__ boxes) {
    __shared__ u64 keys[CAP];
    int bc = blockIdx.x;
    int b  = bc >> 3;
    int tid = threadIdx.x;

    int cnt = g_cnt[bc];
    if (cnt > CAP) cnt = CAP;
    int P = 64;
    while (P < cnt) P <<= 1;

    for (int t = tid; t < P; t += 512) {
        u64 k = 0ull;
        if (t < cnt) {
            u32 sb = __float_as_uint(g_cscore[bc * CAP + t]);
            u32 iv = ~(u32)g_cidx[bc * CAP + t];
            k = ((u64)sb << 32) | (u64)iv;
        }
        keys[t] = k;
    }
    __syncthreads();
    bitonic_desc(keys, P, tid, 512);

    int M = cnt < KP ? cnt : KP;
    if (tid == 0) g_M[bc] = M;

    for (int t = tid; t < M; t += 512) {
        u64 kk = keys[t];
        int idx = (int)(~(u32)kk);
        float4 bp = reinterpret_cast<const float4*>(boxes)[(size_t)(b * NN + idx)];
        int o = bc * KP + t;
        g_sx1[o] = bp.x; g_sy1[o] = bp.y; g_sx2[o] = bp.z; g_sy2[o] = bp.w;
        g_sar[o] = __fmul_rn(__fsub_rn(bp.z, bp.x), __fsub_rn(bp.w, bp.y));
        g_skey[o] = kk;
        g_sidx[o] = idx;
    }
}

// ---------------------------------------------------------------------------
// Triangular IoU mask build, item = (iw, jw) 32x32 tile, 128 slots per bc.
// Division-free exact test: rn(inter/den) > 0.5  <=>  inter - 0.5*den > (0.5*den)*2^-24
#define NSPLIT 16

__global__ void __launch_bounds__(256) k2b_mask() {
    __shared__ float sx1[KP], sy1[KP], sx2[KP], sy2[KP], sar[KP];
    int bc = blockIdx.x >> 4;
    int s  = blockIdx.x & 15;
    int M  = g_M[bc];
    int nW = (M + 31) >> 5;

    for (int t = threadIdx.x; t < KP; t += 256) {
        int o = bc * KP + t;        // rows >= M are zero in global (.bss, never written)
        sx1[t] = g_sx1[o]; sy1[t] = g_sy1[o];
        sx2[t] = g_sx2[o]; sy2[t] = g_sy2[o];
        sar[t] = g_sar[o];
    }
    __syncthreads();

    int w = threadIdx.x >> 5, lane = threadIdx.x & 31;
    int slot = s * 8 + w;            // 0..127
    int e = 0;
    for (int iw = 0; iw < nW; iw++) {
        for (int jw = iw; jw < nW; jw++, e++) {
            if ((e & 127) != slot) continue;
            int j = (jw << 5) + lane;
            float jx1 = sx1[j], jy1 = sy1[j], jx2 = sx2[j], jy2 = sy2[j], ja = sar[j];
            int i0 = iw << 5;
            int dmax = M - i0; if (dmax > 32) dmax = 32;
            bool isdiag = (jw == iw);
            for (int d = 0; d < dmax; d++) {
                int i = i0 + d;
                float ix1 = sx1[i], iy1 = sy1[i], ix2 = sx2[i], iy2 = sy2[i], ia = sar[i];
                float ww = fmaxf(__fsub_rn(fminf(ix2, jx2), fmaxf(ix1, jx1)), 0.0f);
                float hh = fmaxf(__fsub_rn(fminf(iy2, jy2), fmaxf(iy1, jy1)), 0.0f);
                float inter = __fmul_rn(ww, hh);
                float den   = __fsub_rn(__fadd_rn(ia, ja), inter);
                float th    = __fmul_rn(0.5f, den);          // exact
                float diff  = __fsub_rn(inter, th);          // exact (Sterbenz)
                float eps   = __fmul_rn(th, 5.9604645e-8f);  // t * 2^-24, exact
                bool p = (j > i) && (j < M) && (diff > eps);
                u32 mm = __ballot_sync(0xffffffffu, p);
                if (lane == 0) {
                    g_mask[((size_t)bc * KPAD + i) * 32 + jw] = mm;
                    if (isdiag) g_diag[bc * KPAD + i] = mm;
                }
            }
        }
    }
}

// ---------------------------------------------------------------------------
// Greedy scan: one 1024-thread block per (b,c). All warps stage the mask
// global->smem (coalesced), then warp 0 scans from SMEM (LDS 29 cyc) with an
// 8-deep ring. Rows >= M and ring-overshoot rows are zero (never written).
#define K2C_ROWS (KP + 8)
#define K2C_SMEM (K2C_ROWS * 32 * 4 + K2C_ROWS * 4)

__global__ void __launch_bounds__(1024, 1) k2c_scan() {
    extern __shared__ u32 sh[];
    u32* smk = sh;                       // [K2C_ROWS][32]
    u32* sdg = sh + K2C_ROWS * 32;       // [K2C_ROWS]

    int bc  = blockIdx.x;
    int tid = threadIdx.x;
    int c   = bc & 7;
    int M   = g_M[bc];
    if (M == 0) { if (tid == 0) g_kcnt[bc] = 0; return; }
    int nW = (M + 31) >> 5;
    int nrows = (nW << 5) + 8;           // <= 1032 = K2C_ROWS

    const u32* mrow = g_mask + (size_t)bc * KPAD * 32;
    const u32* diag = g_diag + bc * KPAD;

    // cooperative staging (rows >= M are zero in global)
    for (int t = tid; t < nrows * 32; t += 1024) smk[t] = mrow[t];
    for (int t = tid; t < nrows; t += 1024)      sdg[t] = diag[t];
    __syncthreads();

    int w = tid >> 5, lane = tid & 31;
    if (w != 0) return;

    u32 RW[8], DG[8];
#pragma unroll
    for (int d = 0; d < 8; d++) {
        RW[d] = smk[(d << 5) + lane];
        DG[d] = sdg[d];
    }
    u32 remv = 0u, keepreg = 0u;
    for (int g1 = 0; g1 < nW; g1++) {
        u32 cur = __shfl_sync(0xffffffffu, remv, g1);
        u32 kw = 0u;
#pragma unroll
        for (int d = 0; d < 32; d++) {
            int i = (g1 << 5) + d;
            u32 rw = RW[d & 7], dg = DG[d & 7];
            int ip = i + 8;                       // <= nW*32+7 < nrows
            RW[d & 7] = smk[(ip << 5) + lane];
            DG[d & 7] = sdg[ip];
            u32 smask = (u32)((int)(cur << (31 - d)) >> 31);  // all-ones if suppressed
            kw   |= ~smask & (1u << d);
            cur  |= dg & ~smask;
            remv |= rw & ~smask;
        }
        if (lane == g1) keepreg = kw;
    }
    // mask tail bits beyond M
    {
        int lastg = (M - 1) >> 5;
        u32 tail = (M & 31) ? ((1u << (M & 31)) - 1u) : 0xffffffffu;
        if (lane == lastg) keepreg &= tail;
        if (lane > lastg)  keepreg = 0u;
    }

    // compact kept entries (order preserved -> score-sorted), cap 128
    int cntl = __popc(keepreg);
    int pre = cntl;
#pragma unroll
    for (int o = 1; o < 32; o <<= 1) {
        int vv = __shfl_up_sync(0xffffffffu, pre, o);
        if (lane >= o) pre += vv;
    }
    int off = pre - cntl;
    int total = __shfl_sync(0xffffffffu, pre, 31);
    if (lane == 0) g_kcnt[bc] = total < 128 ? total : 128;
    u32 wb = keepreg;
    while (wb && off < 128) {
        int b2 = __ffs(wb) - 1;
        wb &= wb - 1;
        int i = (lane << 5) + b2;
        u64 sk = g_skey[bc * KP + i];
        g_ckey[bc * 128 + off]    = (sk & 0xffffffff00000000ull) | (u64)(~(u32)(c * KP + i));
        g_cidxsel[bc * 128 + off] = g_sidx[bc * KP + i];
        off++;
    }
}

// ---------------------------------------------------------------------------
// Final top-100 by parallel rank-selection over 8 sorted lists of <=128.
__global__ void __launch_bounds__(1024) k3_rank(const float* __restrict__ boxes,
                                                const float* __restrict__ rot,
                                                const float* __restrict__ trans,
                                                float* __restrict__ out) {
    __shared__ u64 lists[8][128];
    __shared__ int written[MAXD];
    int b = blockIdx.x, tid = threadIdx.x;
    int c = tid >> 7, k = tid & 127;
    int bc = b * 8 + c;

    if (tid < 8)    g_cnt[b * 8 + tid] = 0;   // reset for next graph replay
    if (tid < MAXD) written[tid] = 0;

    u64 key = 0ull;
    if (k < g_kcnt[bc]) key = g_ckey[bc * 128 + k];
    lists[c][k] = key;
    __syncthreads();

    float* ob   = out;
    float* os   = out + 3200;
    float* ol   = out + 4000;
    float* orot = out + 4800;
    float* otr  = out + 7200;

    if (key != 0ull) {
        int rank = 0;
#pragma unroll
        for (int c2 = 0; c2 < 8; c2++) {
            const u64* L = lists[c2];
            int lo = 0, hi = 128;
#pragma unroll
            for (int s = 0; s < 8; s++) {
                if (lo < hi) {
                    int mid = (lo + hi) >> 1;
                    if (L[mid] > key) lo = mid + 1; else hi = mid;
                }
            }
            rank += lo;   // count of entries strictly greater than key
        }
        if (rank < MAXD) {
            written[rank] = 1;
            int base = b * MAXD + rank;
            int idx  = g_cidxsel[bc * 128 + k];
            float s  = __uint_as_float((u32)(key >> 32));
            size_t g = (size_t)(b * NN + idx);
            float4 bp = reinterpret_cast<const float4*>(boxes)[g];
            ob[base * 4 + 0] = bp.x;
            ob[base * 4 + 1] = bp.y;
            ob[base * 4 + 2] = bp.z;
            ob[base * 4 + 3] = bp.w;
            os[base] = s;
            ol[base] = (float)c;
            const float* rp = rot + g * 3;
            orot[base * 3 + 0] = rp[0];
            orot[base * 3 + 1] = rp[1];
            orot[base * 3 + 2] = rp[2];
            const float* tp = trans + g * 3;
            otr[base * 3 + 0] = tp[0];
            otr[base * 3 + 1] = tp[1];
            otr[base * 3 + 2] = tp[2];
        }
    }
    __syncthreads();
    if (tid < MAXD && !written[tid]) {
        int base = b * MAXD + tid;
        ob[base * 4 + 0] = -1.0f;
        ob[base * 4 + 1] = -1.0f;
        ob[base * 4 + 2] = -1.0f;
        ob[base * 4 + 3] = -1.0f;
        os[base] = -1.0f;
        ol[base] = -1.0f;
        orot[base * 3 + 0] = -1.0f;
        orot[base * 3 + 1] = -1.0f;
        orot[base * 3 + 2] = -1.0f;
        otr[base * 3 + 0] = -1.0f;
        otr[base * 3 + 1] = -1.0f;
        otr[base * 3 + 2] = -1.0f;
    }
}

// ---------------------------------------------------------------------------
extern "C" void kernel_launch(void* const* d_in, const int* in_sizes, int n_in,
                              void* d_out, int out_size) {
    const float* boxes = (const float*)d_in[0];
    const float* cls   = (const float*)d_in[1];
    const float* rot   = (const float*)d_in[2];
    const float* trans = (const float*)d_in[3];
    float* out = (float*)d_out;

    cudaFuncSetAttribute(k2c_scan, cudaFuncAttributeMaxDynamicSharedMemorySize, K2C_SMEM);

    k1_cand<<<dim3((NN + 511) / 512, BB), 256>>>(cls);
    k2a_sort<<<BB * CC, 512>>>(boxes);
    k2b_mask<<<BB * CC * NSPLIT, 256>>>();
    k2c_scan<<<BB * CC, 1024, K2C_SMEM>>>();
    k3_rank<<<BB, 1024>>>(boxes, rot, trans, out);
}

// round 14
// speedup vs baseline: 4.3274x; 1.1494x over previous
#include <cuda_runtime.h>
#include <cuda_bf16.h>
#include <cstdint>

#define BB 8
#define NN 50000
#define CC 8
#define CAP 2048
#define KP 1024
#define MAXD 100
#define SCORE_THR 0.99f

typedef unsigned long long u64;
typedef unsigned int u32;

// ---------------- device scratch (no allocations allowed) -------------------
__device__ int   g_cnt[BB * CC];          // zero at load; re-zeroed by k3_rank
__device__ float g_cscore[BB * CC * CAP];
__device__ int   g_cidx[BB * CC * CAP];

__device__ int   g_kcnt[BB * CC];
__device__ u64   g_ckey[BB * CC * 128];   // top-128 kept keys per class (sorted)
__device__ int   g_cidxsel[BB * CC * 128];

// ---------------------------------------------------------------------------
// Candidate compaction: 2 points/thread, one batched atomic warp-instr.
__global__ void __launch_bounds__(256) k1_cand(const float* __restrict__ cls) {
    int b  = blockIdx.y;
    int t  = threadIdx.x;
    int n0 = blockIdx.x * 512 + t;       // always < NN for grid.x = 98
    int n1 = n0 + 256;
    bool ok1 = n1 < NN;

    float a[8], dd[8];
    {
        const float4* p = reinterpret_cast<const float4*>(cls + ((size_t)b * NN + n0) * CC);
        float4 x = p[0], y = p[1];
        a[0]=x.x; a[1]=x.y; a[2]=x.z; a[3]=x.w;
        a[4]=y.x; a[5]=y.y; a[6]=y.z; a[7]=y.w;
    }
    if (ok1) {
        const float4* p = reinterpret_cast<const float4*>(cls + ((size_t)b * NN + n1) * CC);
        float4 x = p[0], y = p[1];
        dd[0]=x.x; dd[1]=x.y; dd[2]=x.z; dd[3]=x.w;
        dd[4]=y.x; dd[5]=y.y; dd[6]=y.z; dd[7]=y.w;
    } else {
#pragma unroll
        for (int c = 0; c < 8; c++) dd[c] = 0.0f;
    }

    int lane = t & 31;
    u32 m0[8], m1[8];
    u32 myc0 = 0, myc1 = 0;
#pragma unroll
    for (int c = 0; c < 8; c++) {
        m0[c] = __ballot_sync(0xffffffffu, a[c]  > SCORE_THR);
        m1[c] = __ballot_sync(0xffffffffu, dd[c] > SCORE_THR);
        if (lane == c) { myc0 = m0[c]; myc1 = m1[c]; }
    }
    int tot = __popc(myc0) + __popc(myc1);
    int base = 0;
    if (lane < 8 && tot > 0) base = atomicAdd(&g_cnt[b * 8 + lane], tot);
    u32 lt = (1u << lane) - 1u;
#pragma unroll
    for (int c = 0; c < 8; c++) {
        int basec = __shfl_sync(0xffffffffu, base, c);
        int bcC = (b * 8 + c) * CAP;
        if (a[c] > SCORE_THR) {
            int off = basec + __popc(m0[c] & lt);
            if (off < CAP) { g_cscore[bcC + off] = a[c]; g_cidx[bcC + off] = n0; }
        }
        if (dd[c] > SCORE_THR) {
            int off = basec + __popc(m0[c]) + __popc(m1[c] & lt);
            if (off < CAP) { g_cscore[bcC + off] = dd[c]; g_cidx[bcC + off] = n1; }
        }
    }
}

// ---------------------------------------------------------------------------
__device__ __forceinline__ void bitonic_desc(u64* s, int n, int tid, int nthreads) {
    for (int k = 2; k <= n; k <<= 1) {
        for (int j = k >> 1; j > 0; j >>= 1) {
            for (int i = tid; i < n; i += nthreads) {
                int ixj = i ^ j;
                if (ixj > i) {
                    u64 a = s[i], c = s[ixj];
                    bool up = ((i & k) == 0);
                    if (up ? (a < c) : (a > c)) { s[i] = c; s[ixj] = a; }
                }
            }
            __syncthreads();
        }
    }
}

// ---------------------------------------------------------------------------
// Fused per-(b,c): sort + box gather + IoU mask build (in SMEM) + greedy scan.
// Smem: smk u32[ROWS][32] | sdg u32[ROWS] | boxes 5*KP f32 | keys u64[CAP]
#define K2_ROWS 1032
#define K2_SMEM (K2_ROWS*32*4 + K2_ROWS*4 + 5*KP*4 + CAP*8)

__global__ void __launch_bounds__(1024, 1) k2_fused(const float* __restrict__ boxes) {
    extern __shared__ u32 sh[];
    u32*   smk  = sh;                                   // [K2_ROWS][32]
    u32*   sdg  = sh + K2_ROWS * 32;                    // [K2_ROWS]
    float* sx1  = reinterpret_cast<float*>(sdg + K2_ROWS);
    float* sy1  = sx1 + KP;
    float* sx2  = sy1 + KP;
    float* sy2  = sx2 + KP;
    float* sar  = sy2 + KP;
    u64*   keys = reinterpret_cast<u64*>(sar + KP);

    int bc  = blockIdx.x;
    int b   = bc >> 3;
    int c   = bc & 7;
    int tid = threadIdx.x;

    int cnt = g_cnt[bc];
    if (cnt > CAP) cnt = CAP;
    if (cnt == 0) { if (tid == 0) g_kcnt[bc] = 0; return; }
    int M  = cnt < KP ? cnt : KP;
    int nW = (M + 31) >> 5;
    int nrows = (nW << 5) + 8;               // <= 1032

    int P = 64;
    while (P < cnt) P <<= 1;

    // zero mask + diag, load candidate keys
    for (int t = tid; t < nrows * 32; t += 1024) smk[t] = 0u;
    for (int t = tid; t < nrows; t += 1024)      sdg[t] = 0u;
    for (int t = tid; t < P; t += 1024) {
        u64 k = 0ull;
        if (t < cnt) {
            u32 sb = __float_as_uint(g_cscore[bc * CAP + t]);
            u32 iv = ~(u32)g_cidx[bc * CAP + t];
            k = ((u64)sb << 32) | (u64)iv;
        }
        keys[t] = k;
    }
    __syncthreads();
    bitonic_desc(keys, P, tid, 1024);        // ends with __syncthreads

    // gather sorted candidate boxes
    if (tid < M) {
        int idx = (int)(~(u32)keys[tid]);
        float4 bp = reinterpret_cast<const float4*>(boxes)[(size_t)(b * NN + idx)];
        sx1[tid] = bp.x; sy1[tid] = bp.y; sx2[tid] = bp.z; sy2[tid] = bp.w;
        sar[tid] = __fmul_rn(__fsub_rn(bp.z, bp.x), __fsub_rn(bp.w, bp.y));
    }
    __syncthreads();

    int w = tid >> 5, lane = tid & 31;

    // triangular mask build: tile = (iw, jw), round-robin over 32 warps.
    // Division-free exact test: rn(inter/den)>0.5 <=> inter-0.5*den > (0.5*den)*2^-24
    int e = 0;
    for (int iw = 0; iw < nW; iw++) {
        for (int jw = iw; jw < nW; jw++, e++) {
            if ((e & 31) != w) continue;
            int j = (jw << 5) + lane;
            float jx1 = sx1[j], jy1 = sy1[j], jx2 = sx2[j], jy2 = sy2[j], ja = sar[j];
            int i0 = iw << 5;
            int dmax = M - i0; if (dmax > 32) dmax = 32;
            bool isdiag = (jw == iw);
            for (int d = 0; d < dmax; d++) {
                int i = i0 + d;
                float ix1 = sx1[i], iy1 = sy1[i], ix2 = sx2[i], iy2 = sy2[i], ia = sar[i];
                float ww = fmaxf(__fsub_rn(fminf(ix2, jx2), fmaxf(ix1, jx1)), 0.0f);
                float hh = fmaxf(__fsub_rn(fminf(iy2, jy2), fmaxf(iy1, jy1)), 0.0f);
                float inter = __fmul_rn(ww, hh);
                float den   = __fsub_rn(__fadd_rn(ia, ja), inter);
                float th    = __fmul_rn(0.5f, den);
                float diff  = __fsub_rn(inter, th);
                float eps   = __fmul_rn(th, 5.9604645e-8f);
                bool p = (j > i) && (j < M) && (diff > eps);
                u32 mm = __ballot_sync(0xffffffffu, p);
                if (lane == 0) {
                    smk[(i << 5) + jw] = mm;
                    if (isdiag) sdg[i] = mm;
                }
            }
        }
    }
    __syncthreads();

    // serial greedy scan by warp 0 (R13 structure: LDS-fed 8-deep ring)
    if (w != 0) return;

    u32 RW[8], DG[8];
#pragma unroll
    for (int d = 0; d < 8; d++) {
        RW[d] = smk[(d << 5) + lane];
        DG[d] = sdg[d];
    }
    u32 remv = 0u, keepreg = 0u;
    for (int g1 = 0; g1 < nW; g1++) {
        u32 cur = __shfl_sync(0xffffffffu, remv, g1);
        u32 kw = 0u;
#pragma unroll
        for (int d = 0; d < 32; d++) {
            int i = (g1 << 5) + d;
            u32 rw = RW[d & 7], dg = DG[d & 7];
            int ip = i + 8;                       // < nrows, pad rows are 0
            RW[d & 7] = smk[(ip << 5) + lane];
            DG[d & 7] = sdg[ip];
            u32 smask = (u32)((int)(cur << (31 - d)) >> 31);  // all-ones if suppressed
            kw   |= ~smask & (1u << d);
            cur  |= dg & ~smask;
            remv |= rw & ~smask;
        }
        if (lane == g1) keepreg = kw;
    }
    // mask tail bits beyond M
    {
        int lastg = (M - 1) >> 5;
        u32 tail = (M & 31) ? ((1u << (M & 31)) - 1u) : 0xffffffffu;
        if (lane == lastg) keepreg &= tail;
        if (lane > lastg)  keepreg = 0u;
    }

    // compact kept entries (order preserved -> score-sorted), cap 128
    int cntl = __popc(keepreg);
    int pre = cntl;
#pragma unroll
    for (int o = 1; o < 32; o <<= 1) {
        int vv = __shfl_up_sync(0xffffffffu, pre, o);
        if (lane >= o) pre += vv;
    }
    int off = pre - cntl;
    int total = __shfl_sync(0xffffffffu, pre, 31);
    if (lane == 0) g_kcnt[bc] = total < 128 ? total : 128;
    u32 wb = keepreg;
    while (wb && off < 128) {
        int b2 = __ffs(wb) - 1;
        wb &= wb - 1;
        int i = (lane << 5) + b2;
        u64 sk = keys[i];
        g_ckey[bc * 128 + off]    = (sk & 0xffffffff00000000ull) | (u64)(~(u32)(c * KP + i));
        g_cidxsel[bc * 128 + off] = (int)(~(u32)sk);
        off++;
    }
}

// ---------------------------------------------------------------------------
// Final top-100 by parallel rank-selection over 8 sorted lists of <=128.
__global__ void __launch_bounds__(1024) k3_rank(const float* __restrict__ boxes,
                                                const float* __restrict__ rot,
                                                const float* __restrict__ trans,
                                                float* __restrict__ out) {
    __shared__ u64 lists[8][128];
    __shared__ int written[MAXD];
    int b = blockIdx.x, tid = threadIdx.x;
    int c = tid >> 7, k = tid & 127;
    int bc = b * 8 + c;

    if (tid < 8)    g_cnt[b * 8 + tid] = 0;   // reset for next graph replay
    if (tid < MAXD) written[tid] = 0;

    u64 key = 0ull;
    if (k < g_kcnt[bc]) key = g_ckey[bc * 128 + k];
    lists[c][k] = key;
    __syncthreads();

    float* ob   = out;
    float* os   = out + 3200;
    float* ol   = out + 4000;
    float* orot = out + 4800;
    float* otr  = out + 7200;

    if (key != 0ull) {
        int rank = 0;
#pragma unroll
        for (int c2 = 0; c2 < 8; c2++) {
            const u64* L = lists[c2];
            int lo = 0, hi = 128;
#pragma unroll
            for (int s = 0; s < 8; s++) {
                if (lo < hi) {
                    int mid = (lo + hi) >> 1;
                    if (L[mid] > key) lo = mid + 1; else hi = mid;
                }
            }
            rank += lo;   // count of entries strictly greater than key
        }
        if (rank < MAXD) {
            written[rank] = 1;
            int base = b * MAXD + rank;
            int idx  = g_cidxsel[bc * 128 + k];
            float s  = __uint_as_float((u32)(key >> 32));
            size_t g = (size_t)(b * NN + idx);
            float4 bp = reinterpret_cast<const float4*>(boxes)[g];
            ob[base * 4 + 0] = bp.x;
            ob[base * 4 + 1] = bp.y;
            ob[base * 4 + 2] = bp.z;
            ob[base * 4 + 3] = bp.w;
            os[base] = s;
            ol[base] = (float)c;
            const float* rp = rot + g * 3;
            orot[base * 3 + 0] = rp[0];
            orot[base * 3 + 1] = rp[1];
            orot[base * 3 + 2] = rp[2];
            const float* tp = trans + g * 3;
            otr[base * 3 + 0] = tp[0];
            otr[base * 3 + 1] = tp[1];
            otr[base * 3 + 2] = tp[2];
        }
    }
    __syncthreads();
    if (tid < MAXD && !written[tid]) {
        int base = b * MAXD + tid;
        ob[base * 4 + 0] = -1.0f;
        ob[base * 4 + 1] = -1.0f;
        ob[base * 4 + 2] = -1.0f;
        ob[base * 4 + 3] = -1.0f;
        os[base] = -1.0f;
        ol[base] = -1.0f;
        orot[base * 3 + 0] = -1.0f;
        orot[base * 3 + 1] = -1.0f;
        orot[base * 3 + 2] = -1.0f;
        otr[base * 3 + 0] = -1.0f;
        otr[base * 3 + 1] = -1.0f;
        otr[base * 3 + 2] = -1.0f;
    }
}

// ---------------------------------------------------------------------------
extern "C" void kernel_launch(void* const* d_in, const int* in_sizes, int n_in,
                              void* d_out, int out_size) {
    const float* boxes = (const float*)d_in[0];
    const float* cls   = (const float*)d_in[1];
    const float* rot   = (const float*)d_in[2];
    const float* trans = (const float*)d_in[3];
    float* out = (float*)d_out;

    cudaFuncSetAttribute(k2_fused, cudaFuncAttributeMaxDynamicSharedMemorySize, K2_SMEM);

    k1_cand<<<dim3((NN + 511) / 512, BB), 256>>>(cls);
    k2_fused<<<BB * CC, 1024, K2_SMEM>>>(boxes);
    k3_rank<<<BB, 1024>>>(boxes, rot, trans, out);
}

// round 15
// speedup vs baseline: 4.6195x; 1.0675x over previous
#include <cuda_runtime.h>
#include <cuda_bf16.h>
#include <cstdint>

#define BB 8
#define NN 50000
#define CC 8
#define CAP 2048
#define KP 1024
#define MAXD 100
#define SCORE_THR 0.99f

typedef unsigned long long u64;
typedef unsigned int u32;

// ---------------- device scratch (no allocations allowed) -------------------
__device__ int   g_cnt[BB * CC];          // zero at load; re-zeroed by last block
__device__ float g_cscore[BB * CC * CAP];
__device__ int   g_cidx[BB * CC * CAP];

__device__ int   g_kcnt[BB * CC];
__device__ u64   g_ckey[BB * CC * 128];   // top-128 kept keys per class (sorted)
__device__ int   g_cidxsel[BB * CC * 128];
__device__ int   g_done[BB];              // completion counters (reset each call)

// ---------------------------------------------------------------------------
// Candidate compaction: 4 points/thread (8 LDG.128 in flight), one wave,
// one batched atomic warp-instruction for all 8 classes.
__global__ void __launch_bounds__(256) k1_cand(const float* __restrict__ cls) {
    int b  = blockIdx.y;
    int t  = threadIdx.x;
    int base_n = blockIdx.x * 1024 + t;

    float v[4][8];
#pragma unroll
    for (int p = 0; p < 4; p++) {
        int n = base_n + (p << 8);
        if (n < NN) {
            const float4* ptr = reinterpret_cast<const float4*>(cls + ((size_t)b * NN + n) * CC);
            float4 x = ptr[0], y = ptr[1];
            v[p][0]=x.x; v[p][1]=x.y; v[p][2]=x.z; v[p][3]=x.w;
            v[p][4]=y.x; v[p][5]=y.y; v[p][6]=y.z; v[p][7]=y.w;
        } else {
#pragma unroll
            for (int c = 0; c < 8; c++) v[p][c] = 0.0f;
        }
    }

    int lane = t & 31;
    u32 mm[4][8];
#pragma unroll
    for (int c = 0; c < 8; c++)
#pragma unroll
        for (int p = 0; p < 4; p++)
            mm[p][c] = __ballot_sync(0xffffffffu, v[p][c] > SCORE_THR);

    int tot = 0;
#pragma unroll
    for (int c = 0; c < 8; c++) {
        int s = __popc(mm[0][c]) + __popc(mm[1][c]) + __popc(mm[2][c]) + __popc(mm[3][c]);
        if (lane == c) tot = s;
    }
    int base = 0;
    if (lane < 8 && tot > 0) base = atomicAdd(&g_cnt[b * 8 + lane], tot);

    u32 lt = (1u << lane) - 1u;
#pragma unroll
    for (int c = 0; c < 8; c++) {
        int run = __shfl_sync(0xffffffffu, base, c);
        int bcC = (b * 8 + c) * CAP;
#pragma unroll
        for (int p = 0; p < 4; p++) {
            if (v[p][c] > SCORE_THR) {
                int off = run + __popc(mm[p][c] & lt);
                if (off < CAP) {
                    g_cscore[bcC + off] = v[p][c];
                    g_cidx[bcC + off]   = base_n + (p << 8);
                }
            }
            run += __popc(mm[p][c]);
        }
    }
}

// ---------------------------------------------------------------------------
__device__ __forceinline__ void bitonic_desc(u64* s, int n, int tid, int nthreads) {
    for (int k = 2; k <= n; k <<= 1) {
        for (int j = k >> 1; j > 0; j >>= 1) {
            for (int i = tid; i < n; i += nthreads) {
                int ixj = i ^ j;
                if (ixj > i) {
                    u64 a = s[i], c = s[ixj];
                    bool up = ((i & k) == 0);
                    if (up ? (a < c) : (a > c)) { s[i] = c; s[ixj] = a; }
                }
            }
            __syncthreads();
        }
    }
}

// ---------------------------------------------------------------------------
// Fused per-(b,c): sort + box gather + IoU mask (SMEM) + greedy scan; the
// last-finishing block of each batch also performs the final top-100 + output.
// Smem: smk u32[ROWS][32] | sdg u32[ROWS] | boxes 5*KP f32 | keys u64[CAP]
#define K2_ROWS 1032
#define K2_SMEM (K2_ROWS*32*4 + K2_ROWS*4 + 5*KP*4 + CAP*8)

__global__ void __launch_bounds__(1024, 1) k2_fused(const float* __restrict__ boxes,
                                                    const float* __restrict__ rot,
                                                    const float* __restrict__ trans,
                                                    float* __restrict__ out) {
    extern __shared__ u32 sh[];
    u32*   smk  = sh;                                   // [K2_ROWS][32]
    u32*   sdg  = sh + K2_ROWS * 32;                    // [K2_ROWS]
    float* sx1  = reinterpret_cast<float*>(sdg + K2_ROWS);
    float* sy1  = sx1 + KP;
    float* sx2  = sy1 + KP;
    float* sy2  = sx2 + KP;
    float* sar  = sy2 + KP;
    u64*   keys = reinterpret_cast<u64*>(sar + KP);

    int bc  = blockIdx.x;
    int b   = bc >> 3;
    int c   = bc & 7;
    int tid = threadIdx.x;
    int w   = tid >> 5, lane = tid & 31;

    int cnt = g_cnt[bc];
    if (cnt > CAP) cnt = CAP;

    if (cnt > 0) {
        int M  = cnt < KP ? cnt : KP;
        int nW = (M + 31) >> 5;
        int nrows = (nW << 5) + 8;               // <= 1032

        int P = 64;
        while (P < cnt) P <<= 1;

        // zero mask + diag, load candidate keys
        for (int t = tid; t < nrows * 32; t += 1024) smk[t] = 0u;
        for (int t = tid; t < nrows; t += 1024)      sdg[t] = 0u;
        for (int t = tid; t < P; t += 1024) {
            u64 k = 0ull;
            if (t < cnt) {
                u32 sb = __float_as_uint(g_cscore[bc * CAP + t]);
                u32 iv = ~(u32)g_cidx[bc * CAP + t];
                k = ((u64)sb << 32) | (u64)iv;
            }
            keys[t] = k;
        }
        __syncthreads();
        bitonic_desc(keys, P, tid, 1024);        // ends with __syncthreads

        // gather sorted candidate boxes
        if (tid < M) {
            int idx = (int)(~(u32)keys[tid]);
            float4 bp = reinterpret_cast<const float4*>(boxes)[(size_t)(b * NN + idx)];
            sx1[tid] = bp.x; sy1[tid] = bp.y; sx2[tid] = bp.z; sy2[tid] = bp.w;
            sar[tid] = __fmul_rn(__fsub_rn(bp.z, bp.x), __fsub_rn(bp.w, bp.y));
        }
        __syncthreads();

        // triangular mask build: tile = (iw, jw), round-robin over 32 warps.
        // Division-free exact: rn(inter/den)>0.5 <=> inter-0.5*den > (0.5*den)*2^-24
        int e = 0;
        for (int iw = 0; iw < nW; iw++) {
            for (int jw = iw; jw < nW; jw++, e++) {
                if ((e & 31) != w) continue;
                int j = (jw << 5) + lane;
                float jx1 = sx1[j], jy1 = sy1[j], jx2 = sx2[j], jy2 = sy2[j], ja = sar[j];
                int i0 = iw << 5;
                int dmax = M - i0; if (dmax > 32) dmax = 32;
                bool isdiag = (jw == iw);
                for (int d = 0; d < dmax; d++) {
                    int i = i0 + d;
                    float ix1 = sx1[i], iy1 = sy1[i], ix2 = sx2[i], iy2 = sy2[i], ia = sar[i];
                    float ww = fmaxf(__fsub_rn(fminf(ix2, jx2), fmaxf(ix1, jx1)), 0.0f);
                    float hh = fmaxf(__fsub_rn(fminf(iy2, jy2), fmaxf(iy1, jy1)), 0.0f);
                    float inter = __fmul_rn(ww, hh);
                    float den   = __fsub_rn(__fadd_rn(ia, ja), inter);
                    float th    = __fmul_rn(0.5f, den);
                    float diff  = __fsub_rn(inter, th);
                    float eps   = __fmul_rn(th, 5.9604645e-8f);
                    bool p = (j > i) && (j < M) && (diff > eps);
                    u32 mmv = __ballot_sync(0xffffffffu, p);
                    if (lane == 0) {
                        smk[(i << 5) + jw] = mmv;
                        if (isdiag) sdg[i] = mmv;
                    }
                }
            }
        }
        __syncthreads();

        // serial greedy scan by warp 0 (LDS-fed 8-deep ring)
        if (w == 0) {
            u32 RW[8], DG[8];
#pragma unroll
            for (int d = 0; d < 8; d++) {
                RW[d] = smk[(d << 5) + lane];
                DG[d] = sdg[d];
            }
            u32 remv = 0u, keepreg = 0u;
            for (int g1 = 0; g1 < nW; g1++) {
                u32 cur = __shfl_sync(0xffffffffu, remv, g1);
                u32 kw = 0u;
#pragma unroll
                for (int d = 0; d < 32; d++) {
                    int i = (g1 << 5) + d;
                    u32 rw = RW[d & 7], dg = DG[d & 7];
                    int ip = i + 8;                       // < nrows, pad rows are 0
                    RW[d & 7] = smk[(ip << 5) + lane];
                    DG[d & 7] = sdg[ip];
                    u32 smask = (u32)((int)(cur << (31 - d)) >> 31);
                    kw   |= ~smask & (1u << d);
                    cur  |= dg & ~smask;
                    remv |= rw & ~smask;
                }
                if (lane == g1) keepreg = kw;
            }
            // mask tail bits beyond M
            {
                int lastg = (M - 1) >> 5;
                u32 tail = (M & 31) ? ((1u << (M & 31)) - 1u) : 0xffffffffu;
                if (lane == lastg) keepreg &= tail;
                if (lane > lastg)  keepreg = 0u;
            }
            // compact kept entries (order preserved -> score-sorted), cap 128
            int cntl = __popc(keepreg);
            int pre = cntl;
#pragma unroll
            for (int o = 1; o < 32; o <<= 1) {
                int vv = __shfl_up_sync(0xffffffffu, pre, o);
                if (lane >= o) pre += vv;
            }
            int off = pre - cntl;
            int total = __shfl_sync(0xffffffffu, pre, 31);
            if (lane == 0) g_kcnt[bc] = total < 128 ? total : 128;
            u32 wb = keepreg;
            while (wb && off < 128) {
                int b2 = __ffs(wb) - 1;
                wb &= wb - 1;
                int i = (lane << 5) + b2;
                u64 sk = keys[i];
                g_ckey[bc * 128 + off]    = (sk & 0xffffffff00000000ull) | (u64)(~(u32)(c * KP + i));
                g_cidxsel[bc * 128 + off] = (int)(~(u32)sk);
                off++;
            }
        }
    } else {
        if (tid == 0) g_kcnt[bc] = 0;
    }
    __syncthreads();

    // ---- completion protocol (canonical threadFenceReduction pattern) ----
    __shared__ int s_last;
    if (tid == 0) {
        __threadfence();
        int vdone = atomicAdd(&g_done[b], 1);
        s_last = (vdone == 7) ? 1 : 0;
    }
    __syncthreads();
    if (!s_last) return;

    // last block of batch b: reset counters, then final top-100 + output
    if (tid == 0)  g_done[b] = 0;
    if (tid < 8)   g_cnt[b * 8 + tid] = 0;

    u64* lists   = reinterpret_cast<u64*>(sh);      // [8][128] overlay
    int* written = reinterpret_cast<int*>(sh + 2048);

    int c2 = tid >> 7, k2 = tid & 127;
    int bck = b * 8 + c2;
    u64 key = 0ull;
    if (k2 < g_kcnt[bck]) key = g_ckey[bck * 128 + k2];
    lists[c2 * 128 + k2] = key;
    if (tid < MAXD) written[tid] = 0;
    __syncthreads();

    float* ob   = out;
    float* os   = out + 3200;
    float* ol   = out + 4000;
    float* orot = out + 4800;
    float* otr  = out + 7200;

    if (key != 0ull) {
        int rank = 0;
#pragma unroll
        for (int cc = 0; cc < 8; cc++) {
            const u64* L = lists + cc * 128;
            int lo = 0, hi = 128;
#pragma unroll
            for (int s = 0; s < 8; s++) {
                if (lo < hi) {
                    int mid = (lo + hi) >> 1;
                    if (L[mid] > key) lo = mid + 1; else hi = mid;
                }
            }
            rank += lo;   // count of entries strictly greater than key
        }
        if (rank < MAXD) {
            written[rank] = 1;
            int base = b * MAXD + rank;
            int idx  = g_cidxsel[bck * 128 + k2];
            float s  = __uint_as_float((u32)(key >> 32));
            size_t g = (size_t)(b * NN + idx);
            float4 bp = reinterpret_cast<const float4*>(boxes)[g];
            ob[base * 4 + 0] = bp.x;
            ob[base * 4 + 1] = bp.y;
            ob[base * 4 + 2] = bp.z;
            ob[base * 4 + 3] = bp.w;
            os[base] = s;
            ol[base] = (float)c2;
            const float* rp = rot + g * 3;
            orot[base * 3 + 0] = rp[0];
            orot[base * 3 + 1] = rp[1];
            orot[base * 3 + 2] = rp[2];
            const float* tp = trans + g * 3;
            otr[base * 3 + 0] = tp[0];
            otr[base * 3 + 1] = tp[1];
            otr[base * 3 + 2] = tp[2];
        }
    }
    __syncthreads();
    if (tid < MAXD && !written[tid]) {
        int base = b * MAXD + tid;
        ob[base * 4 + 0] = -1.0f;
        ob[base * 4 + 1] = -1.0f;
        ob[base * 4 + 2] = -1.0f;
        ob[base * 4 + 3] = -1.0f;
        os[base] = -1.0f;
        ol[base] = -1.0f;
        orot[base * 3 + 0] = -1.0f;
        orot[base * 3 + 1] = -1.0f;
        orot[base * 3 + 2] = -1.0f;
        otr[base * 3 + 0] = -1.0f;
        otr[base * 3 + 1] = -1.0f;
        otr[base * 3 + 2] = -1.0f;
    }
}

// ---------------------------------------------------------------------------
extern "C" void kernel_launch(void* const* d_in, const int* in_sizes, int n_in,
                              void* d_out, int out_size) {
    const float* boxes = (const float*)d_in[0];
    const float* cls   = (const float*)d_in[1];
    const float* rot   = (const float*)d_in[2];
    const float* trans = (const float*)d_in[3];
    float* out = (float*)d_out;

    cudaFuncSetAttribute(k2_fused, cudaFuncAttributeMaxDynamicSharedMemorySize, K2_SMEM);

    k1_cand<<<dim3((NN + 1023) / 1024, BB), 256>>>(cls);
    k2_fused<<<BB * CC, 1024, K2_SMEM>>>(boxes, rot, trans, out);
}

// round 17
// speedup vs baseline: 7.1399x; 1.5456x over previous
#include <cuda_runtime.h>
#include <cuda_bf16.h>
#include <cstdint>

#define BB 8
#define NN 50000
#define CC 8
#define CAP 2048
#define KP 1024
#define MAXD 100
#define SCORE_THR 0.99f

typedef unsigned long long u64;
typedef unsigned int u32;

// ---------------- device scratch (no allocations allowed) -------------------
__device__ int   g_cnt[BB * CC];          // zero at load; re-zeroed by last block
__device__ float g_cscore[BB * CC * CAP];
__device__ int   g_cidx[BB * CC * CAP];

__device__ int   g_kcnt[BB * CC];
__device__ u64   g_ckey[BB * CC * 128];   // top-128 kept keys per class (sorted)
__device__ int   g_cidxsel[BB * CC * 128];
__device__ int   g_done[BB];              // completion counters (reset each call)

// ---------------------------------------------------------------------------
// Candidate compaction: 4 points/thread (8 LDG.128 in flight), one wave,
// one batched atomic warp-instruction for all 8 classes.
__global__ void __launch_bounds__(256) k1_cand(const float* __restrict__ cls) {
    int b  = blockIdx.y;
    int t  = threadIdx.x;
    int base_n = blockIdx.x * 1024 + t;

    float v[4][8];
#pragma unroll
    for (int p = 0; p < 4; p++) {
        int n = base_n + (p << 8);
        if (n < NN) {
            const float4* ptr = reinterpret_cast<const float4*>(cls + ((size_t)b * NN + n) * CC);
            float4 x = ptr[0], y = ptr[1];
            v[p][0]=x.x; v[p][1]=x.y; v[p][2]=x.z; v[p][3]=x.w;
            v[p][4]=y.x; v[p][5]=y.y; v[p][6]=y.z; v[p][7]=y.w;
        } else {
#pragma unroll
            for (int c = 0; c < 8; c++) v[p][c] = 0.0f;
        }
    }

    int lane = t & 31;
    u32 mm[4][8];
#pragma unroll
    for (int c = 0; c < 8; c++)
#pragma unroll
        for (int p = 0; p < 4; p++)
            mm[p][c] = __ballot_sync(0xffffffffu, v[p][c] > SCORE_THR);

    int tot = 0;
#pragma unroll
    for (int c = 0; c < 8; c++) {
        int s = __popc(mm[0][c]) + __popc(mm[1][c]) + __popc(mm[2][c]) + __popc(mm[3][c]);
        if (lane == c) tot = s;
    }
    int base = 0;
    if (lane < 8 && tot > 0) base = atomicAdd(&g_cnt[b * 8 + lane], tot);

    u32 lt = (1u << lane) - 1u;
#pragma unroll
    for (int c = 0; c < 8; c++) {
        int run = __shfl_sync(0xffffffffu, base, c);
        int bcC = (b * 8 + c) * CAP;
#pragma unroll
        for (int p = 0; p < 4; p++) {
            if (v[p][c] > SCORE_THR) {
                int off = run + __popc(mm[p][c] & lt);
                if (off < CAP) {
                    g_cscore[bcC + off] = v[p][c];
                    g_cidx[bcC + off]   = base_n + (p << 8);
                }
            }
            run += __popc(mm[p][c]);
        }
    }
}

// ---------------------------------------------------------------------------
__device__ __forceinline__ void bitonic_desc(u64* s, int n, int tid, int nthreads) {
    for (int k = 2; k <= n; k <<= 1) {
        for (int j = k >> 1; j > 0; j >>= 1) {
            for (int i = tid; i < n; i += nthreads) {
                int ixj = i ^ j;
                if (ixj > i) {
                    u64 a = s[i], c = s[ixj];
                    bool up = ((i & k) == 0);
                    if (up ? (a < c) : (a > c)) { s[i] = c; s[ixj] = a; }
                }
            }
            __syncthreads();
        }
    }
}

// ---------------------------------------------------------------------------
// Fused per-(b,c): sort + gather + chunked column-panel mask build + PULL-model
// greedy scan with early stop at 128 kept; last block per batch emits output.
// Pull model: at group g, cur = OR over kept rows i of smk[i][g] (column g is
// built by the time group g is scanned); serial chain is diag-only.
// Smem: smk u32[ROWS][32] | sdg u32[ROWS] | sbox float4[KP] | sar f32[KP]
//       | keys u64[CAP] | skept int[256]
#define K2_ROWS 1032
#define K2_SMEM (K2_ROWS*32*4 + K2_ROWS*4 + KP*16 + KP*4 + CAP*8 + 256*4)

__global__ void __launch_bounds__(1024, 1) k2_fused(const float* __restrict__ boxes,
                                                    const float* __restrict__ rot,
                                                    const float* __restrict__ trans,
                                                    float* __restrict__ out) {
    extern __shared__ u32 sh[];
    u32*    smk   = sh;                                   // [K2_ROWS][32]
    u32*    sdg   = sh + K2_ROWS * 32;                    // [K2_ROWS]
    float4* sbox  = reinterpret_cast<float4*>(sdg + K2_ROWS);
    float*  sar   = reinterpret_cast<float*>(sbox + KP);
    u64*    keys  = reinterpret_cast<u64*>(sar + KP);
    int*    skept = reinterpret_cast<int*>(keys + CAP);   // kept rows, score order

    __shared__ int s_stop;

    int bc  = blockIdx.x;
    int b   = bc >> 3;
    int c   = bc & 7;
    int tid = threadIdx.x;
    int w   = tid >> 5, lane = tid & 31;

    int cnt = g_cnt[bc];
    if (cnt > CAP) cnt = CAP;

    if (cnt > 0) {
        int M  = cnt < KP ? cnt : KP;
        int nW = (M + 31) >> 5;
        int nrows = (nW << 5) + 8;               // <= 1032

        int P = 64;
        while (P < cnt) P <<= 1;

        // zero mask + diag (uint4), load candidate keys
        {
            uint4 z = make_uint4(0,0,0,0);
            uint4* m4 = reinterpret_cast<uint4*>(smk);
            int nz = (nrows * 32) >> 2;
            for (int t = tid; t < nz; t += 1024) m4[t] = z;
            for (int t = tid; t < nrows; t += 1024) sdg[t] = 0u;
        }
        if (tid == 0) s_stop = 0;
        for (int t = tid; t < P; t += 1024) {
            u64 k = 0ull;
            if (t < cnt) {
                u32 sb = __float_as_uint(g_cscore[bc * CAP + t]);
                u32 iv = ~(u32)g_cidx[bc * CAP + t];
                k = ((u64)sb << 32) | (u64)iv;
            }
            keys[t] = k;
        }
        __syncthreads();
        bitonic_desc(keys, P, tid, 1024);        // ends with __syncthreads

        // gather sorted candidate boxes (float4 + area)
        if (tid < M) {
            int idx = (int)(~(u32)keys[tid]);
            float4 bp = reinterpret_cast<const float4*>(boxes)[(size_t)(b * NN + idx)];
            sbox[tid] = bp;
            sar[tid] = __fmul_rn(__fsub_rn(bp.z, bp.x), __fsub_rn(bp.w, bp.y));
        }
        __syncthreads();

        int lastg = (M - 1) >> 5;
        u32 tailm = (M & 31) ? ((1u << (M & 31)) - 1u) : 0xffffffffu;
        int kbase = 0;                           // uniform in warp 0

        int nChunk = (nW + 1) >> 1;
        for (int cb = 0; cb < nChunk; cb++) {
            // ---- build column panel: tiles (iw <= jw), jw in {2cb, 2cb+1} ----
            int e = 0;
            for (int jw = (cb << 1); jw < (cb << 1) + 2 && jw < nW; jw++) {
                for (int iw = 0; iw <= jw; iw++, e++) {
                    if ((e & 31) != w) continue;
                    int j = (jw << 5) + lane;
                    float4 jb = sbox[j];
                    float  ja = sar[j];
                    int i0 = iw << 5;
                    int dmax = M - i0; if (dmax > 32) dmax = 32;
                    bool isdiag = (jw == iw);
                    for (int d = 0; d < dmax; d++) {
                        int i = i0 + d;
                        float4 ib = sbox[i];
                        float  ia = sar[i];
                        float ww = fmaxf(__fsub_rn(fminf(ib.z, jb.z), fmaxf(ib.x, jb.x)), 0.0f);
                        float hh = fmaxf(__fsub_rn(fminf(ib.w, jb.w), fmaxf(ib.y, jb.y)), 0.0f);
                        float inter = __fmul_rn(ww, hh);
                        float den   = __fsub_rn(__fadd_rn(ia, ja), inter);
                        float th    = __fmul_rn(0.5f, den);
                        float diff  = __fsub_rn(inter, th);
                        float eps   = __fmul_rn(th, 5.9604645e-8f);
                        bool p = (j > i) && (j < M) && (diff > eps);
                        u32 mmv = __ballot_sync(0xffffffffu, p);
                        if (lane == 0) {
                            smk[(i << 5) + jw] = mmv;
                            if (isdiag) sdg[i] = mmv;
                        }
                    }
                }
            }
            __syncthreads();

            // ---- scan groups 2cb, 2cb+1 (warp 0): pull + diag-only chain ----
            if (w == 0) {
#pragma unroll
                for (int sub = 0; sub < 2; sub++) {
                    int g1 = (cb << 1) + sub;
                    if (g1 < nW) {
                        // preload diag words (independent broadcast LDS)
                        u32 DG[32];
#pragma unroll
                        for (int d = 0; d < 32; d++) DG[d] = sdg[(g1 << 5) + d];
                        // pull suppression of this group by all earlier kept rows
                        u32 cur = 0u;
                        for (int t = lane; t < kbase; t += 32)
                            cur |= smk[(skept[t] << 5) + g1];
#pragma unroll
                        for (int o = 16; o > 0; o >>= 1)
                            cur |= __shfl_xor_sync(0xffffffffu, cur, o);
                        // diag-only serial chain
                        u32 kw = 0u;
#pragma unroll
                        for (int d = 0; d < 32; d++) {
                            u32 smask = (u32)((int)(cur << (31 - d)) >> 31);
                            kw  |= ~smask & (1u << d);
                            cur |= DG[d] & ~smask;
                        }
                        if (g1 == lastg) kw &= tailm;
                        // append kept rows (score order preserved)
                        int ck = __popc(kw);
                        if (lane < ck)
                            skept[kbase + lane] = (g1 << 5) + (int)__fns(kw, 0, lane + 1);
                        kbase += ck;
                    }
                }
                if (lane == 0 && kbase >= 128) s_stop = 1;
            }
            __syncthreads();
            if (s_stop) break;
        }

        // compact kept entries from skept (already score-sorted), cap 128
        if (w == 0) {
            int kout = kbase < 128 ? kbase : 128;
            if (lane == 0) g_kcnt[bc] = kout;
            for (int t = lane; t < kout; t += 32) {
                int i = skept[t];
                u64 sk = keys[i];
                g_ckey[bc * 128 + t]    = (sk & 0xffffffff00000000ull) | (u64)(~(u32)(c * KP + i));
                g_cidxsel[bc * 128 + t] = (int)(~(u32)sk);
            }
        }
    } else {
        if (tid == 0) g_kcnt[bc] = 0;
    }
    __syncthreads();

    // ---- completion protocol (canonical threadFenceReduction pattern) ----
    __shared__ int s_last;
    if (tid == 0) {
        __threadfence();
        int vdone = atomicAdd(&g_done[b], 1);
        s_last = (vdone == 7) ? 1 : 0;
    }
    __syncthreads();
    if (!s_last) return;

    // last block of batch b: reset counters, then final top-100 + output
    if (tid == 0)  g_done[b] = 0;
    if (tid < 8)   g_cnt[b * 8 + tid] = 0;

    u64* lists   = reinterpret_cast<u64*>(sh);      // [8][128] overlay
    int* written = reinterpret_cast<int*>(sh + 2048);

    int c2 = tid >> 7, k2 = tid & 127;
    int bck = b * 8 + c2;
    u64 key = 0ull;
    if (k2 < g_kcnt[bck]) key = g_ckey[bck * 128 + k2];
    lists[c2 * 128 + k2] = key;
    if (tid < MAXD) written[tid] = 0;
    __syncthreads();

    float* ob   = out;
    float* os   = out + 3200;
    float* ol   = out + 4000;
    float* orot = out + 4800;
    float* otr  = out + 7200;

    if (key != 0ull) {
        int rank = 0;
#pragma unroll
        for (int cc = 0; cc < 8; cc++) {
            const u64* L = lists + cc * 128;
            int lo = 0, hi = 128;
#pragma unroll
            for (int s = 0; s < 8; s++) {
                if (lo < hi) {
                    int mid = (lo + hi) >> 1;
                    if (L[mid] > key) lo = mid + 1; else hi = mid;
                }
            }
            rank += lo;   // count of entries strictly greater than key
        }
        if (rank < MAXD) {
            written[rank] = 1;
            int base = b * MAXD + rank;
            int idx  = g_cidxsel[bck * 128 + k2];
            float s  = __uint_as_float((u32)(key >> 32));
            size_t g = (size_t)(b * NN + idx);
            float4 bp = reinterpret_cast<const float4*>(boxes)[g];
            ob[base * 4 + 0] = bp.x;
            ob[base * 4 + 1] = bp.y;
            ob[base * 4 + 2] = bp.z;
            ob[base * 4 + 3] = bp.w;
            os[base] = s;
            ol[base] = (float)c2;
            const float* rp = rot + g * 3;
            orot[base * 3 + 0] = rp[0];
            orot[base * 3 + 1] = rp[1];
            orot[base * 3 + 2] = rp[2];
            const float* tp = trans + g * 3;
            otr[base * 3 + 0] = tp[0];
            otr[base * 3 + 1] = tp[1];
            otr[base * 3 + 2] = tp[2];
        }
    }
    __syncthreads();
    if (tid < MAXD && !written[tid]) {
        int base = b * MAXD + tid;
        ob[base * 4 + 0] = -1.0f;
        ob[base * 4 + 1] = -1.0f;
        ob[base * 4 + 2] = -1.0f;
        ob[base * 4 + 3] = -1.0f;
        os[base] = -1.0f;
        ol[base] = -1.0f;
        orot[base * 3 + 0] = -1.0f;
        orot[base * 3 + 1] = -1.0f;
        orot[base * 3 + 2] = -1.0f;
        otr[base * 3 + 0] = -1.0f;
        otr[base * 3 + 1] = -1.0f;
        otr[base * 3 + 2] = -1.0f;
    }
}

// ---------------------------------------------------------------------------
extern "C" void kernel_launch(void* const* d_in, const int* in_sizes, int n_in,
                              void* d_out, int out_size) {
    const float* boxes = (const float*)d_in[0];
    const float* cls   = (const float*)d_in[1];
    const float* rot   = (const float*)d_in[2];
    const float* trans = (const float*)d_in[3];
    float* out = (float*)d_out;

    cudaFuncSetAttribute(k2_fused, cudaFuncAttributeMaxDynamicSharedMemorySize, K2_SMEM);

    k1_cand<<<dim3((NN + 1023) / 1024, BB), 256>>>(cls);
    k2_fused<<<BB * CC, 1024, K2_SMEM>>>(boxes, rot, trans, out);
}